// round 4
// baseline (speedup 1.0000x reference)
#include <cuda_runtime.h>

// GAT_28295244546247 — fused single kernel, v4.
// Analytic collapse (R0): softmax row-constant cancels => identical output rows;
// layer2 softmax exactly uniform; a2_w/a2_b have no effect.
// v4: grid 64x512 (halve sync fan-in + fold chain), tail via mean-first algebra
//     (one 64x64 matvec), W2/b2 staged inside the poll window.

#define NH    8
#define NBLK  64
#define RPB   64
#define NT    512
#define F_OUT 32

__device__ float    g_q[NH * 64];   // RED accumulators (zeroed init / by last exiter)
__device__ float    g_Z[NH];
__device__ unsigned g_arrive = 0;
__device__ unsigned g_exit   = 0;

__global__ __launch_bounds__(NT) void gat_fused(
    const float* __restrict__ x,   const float* __restrict__ W1,
    const float* __restrict__ b1,  const float* __restrict__ a1w,
    const float* __restrict__ a1b, const float* __restrict__ W2,
    const float* __restrict__ b2,  float* __restrict__ out)
{
    __shared__ float W1s[64 * 65];                  // padded, conflict-free both axes
    __shared__ __align__(16) float W2s[F_OUT * 64];
    __shared__ __align__(16) float a1wjs[NH * 64];  // a1w[:,64:128]
    __shared__ __align__(16) float b1s[64];
    __shared__ __align__(16) float b2s[F_OUT];
    __shared__ __align__(16) float us[NH * 64];     // folded u
    __shared__ float cs[NH];
    __shared__ float xs[RPB * 65];
    __shared__ float es[RPB * NH];
    __shared__ float qs[NH * 64];
    __shared__ float qbar[64];
    __shared__ float os[64];
    __shared__ float fs[F_OUT];
    __shared__ int   s_last;

    const int t = threadIdx.x;
    const int b = blockIdx.x;
    const int g = t >> 3, u = t & 7;

    // ---- issue x loads FIRST (latency overlaps all weight staging + fold) ----
    const float4* xr = (const float4*)(x + (b * RPB + g) * 64 + u * 8);
    float4 x0 = xr[0], x1 = xr[1];

    // ---- stage phase-1 weights (coalesced float4) ----
    {
        const float4* w4 = (const float4*)W1;
        #pragma unroll
        for (int r = 0; r < 2; r++) {
            int i = t + r * NT;
            float4 v = w4[i];
            int f = i >> 4, k = (i & 15) << 2;
            float* d = &W1s[f * 65 + k];
            d[0] = v.x; d[1] = v.y; d[2] = v.z; d[3] = v.w;
        }
        if (t < 128) {
            int h = t >> 4, q = t & 15;
            ((float4*)a1wjs)[h * 16 + q] = ((const float4*)a1w)[h * 32 + 16 + q];
        } else if (t < 144) {
            ((float4*)b1s)[t - 128] = ((const float4*)b1)[t - 128];
        }
        if (t < NH * 64 / 4) ((float4*)qs)[t] = make_float4(0.f, 0.f, 0.f, 0.f);
    }
    // park x in smem for the q-accumulation phase
    {
        float* xd = &xs[g * 65 + u * 8];
        xd[0] = x0.x; xd[1] = x0.y; xd[2] = x0.z; xd[3] = x0.w;
        xd[4] = x1.x; xd[5] = x1.y; xd[6] = x1.z; xd[7] = x1.w;
    }
    __syncthreads();

    // ---- fold (1 element/thread): u[h][k] = a1wj[h] . W1[:,k] ----
    {
        const int h = t >> 6, k = t & 63;
        const float* ar = &a1wjs[h * 64];
        float s = 0.f;
        #pragma unroll 16
        for (int f = 0; f < 64; f++) s += ar[f] * W1s[f * 65 + k];
        us[t] = s;
    }
    if (t < NH) {
        float s = a1b[t];
        #pragma unroll 16
        for (int f = 0; f < 64; f++) s += a1wjs[t * 64 + f] * b1s[f];
        cs[t] = s;
    }
    __syncthreads();

    // ---- scores: 8 threads/row on register-resident x, shfl reduce, exp ----
    {
        float s[NH];
        #pragma unroll
        for (int h = 0; h < NH; h++) {
            float4 u0 = ((const float4*)us)[h * 16 + u * 2];
            float4 u1 = ((const float4*)us)[h * 16 + u * 2 + 1];
            s[h] = u0.x * x0.x + u0.y * x0.y + u0.z * x0.z + u0.w * x0.w
                 + u1.x * x1.x + u1.y * x1.y + u1.z * x1.z + u1.w * x1.w;
        }
        #pragma unroll
        for (int o = 1; o < 8; o <<= 1) {
            #pragma unroll
            for (int h = 0; h < NH; h++)
                s[h] += __shfl_xor_sync(0xffffffffu, s[h], o);
        }
        float sv = s[0];
        #pragma unroll
        for (int h = 1; h < NH; h++) sv = (u == h) ? s[h] : sv;
        es[t] = __expf(sv + cs[u]);             // es[g*8+u]
    }
    __syncthreads();

    // ---- block partial q[h][f] = sum_j e[j,h] x[j,f] (f-parallel, 8 j-lanes) ----
    {
        const int f = t & 63, l = t >> 6;
        float acc[NH];
        #pragma unroll
        for (int h = 0; h < NH; h++) acc[h] = 0.f;
        #pragma unroll
        for (int jj = l; jj < RPB; jj += 8) {
            float xv = xs[jj * 65 + f];
            #pragma unroll
            for (int h = 0; h < NH; h++) acc[h] += es[jj * 8 + h] * xv;
        }
        #pragma unroll
        for (int h = 0; h < NH; h++) atomicAdd(&qs[h * 64 + f], acc[h]);
    }
    __syncthreads();

    // ---- publish via RED atomics (1 per thread) ----
    atomicAdd(&g_q[t], qs[t]);
    if (t < NH) {
        float z = 0.f;
        #pragma unroll
        for (int jj = 0; jj < RPB; jj++) z += es[jj * 8 + t];
        atomicAdd(&g_Z[t], z);
    }
    __threadfence();
    __syncthreads();
    if (t == 0) atomicAdd(&g_arrive, 1);        // arrive ASAP

    // ---- stage W2/b2 inside the poll window (free latency) ----
    ((float4*)W2s)[t] = ((const float4*)W2)[t];                 // 512 float4
    if (t < NH) ((float4*)b2s)[t] = ((const float4*)b2)[t];

    if (t == 0) {
        while (*(volatile unsigned*)&g_arrive < NBLK) __nanosleep(32);
    }
    __syncthreads();
    __threadfence();

    // ---- tail: qbar = (1/NH) sum_h q[h]/Z[h]; m = W1 qbar + b1; elu; W2; lrelu ----
    if (t < 64) {
        float s = 0.f;
        #pragma unroll
        for (int h = 0; h < NH; h++) s += g_q[h * 64 + t] / g_Z[h];
        qbar[t] = s * (1.f / NH);
    }
    __syncthreads();
    if (t < 64) {
        float s = b1s[t];
        #pragma unroll 16
        for (int k = 0; k < 64; k++) s += W1s[t * 65 + k] * qbar[k];
        float lr = s > 0.f ? s : 0.2f * s;
        os[t] = lr > 0.f ? lr : (__expf(lr) - 1.f);
    }
    __syncthreads();
    if (t < F_OUT) {
        float s = b2s[t];
        #pragma unroll 16
        for (int f = 0; f < 64; f++) s += W2s[t * 64 + f] * os[f];
        fs[t] = s > 0.f ? s : 0.2f * s;
    }
    __syncthreads();

    // ---- broadcast final row to this block's 64 output rows (1 float4/thread) ----
    {
        int f0 = (t & 7) << 2;
        float4 v = make_float4(fs[f0], fs[f0 + 1], fs[f0 + 2], fs[f0 + 3]);
        ((float4*)out)[b * NT + t] = v;
    }

    // ---- reset accumulators for next graph replay (last exiting block) ----
    __syncthreads();
    if (t == 0) s_last = (atomicAdd(&g_exit, 1) == NBLK - 1);
    __syncthreads();
    if (s_last) {
        g_q[t] = 0.f;
        if (t < NH) g_Z[t] = 0.f;
        if (t == 0) { g_arrive = 0; g_exit = 0; }
    }
}

extern "C" void kernel_launch(void* const* d_in, const int* in_sizes, int n_in,
                              void* d_out, int out_size) {
    const float* x   = (const float*)d_in[0];
    const float* W1  = (const float*)d_in[1];
    const float* b1  = (const float*)d_in[2];
    const float* a1w = (const float*)d_in[3];
    const float* a1b = (const float*)d_in[4];
    const float* W2  = (const float*)d_in[5];
    const float* b2  = (const float*)d_in[6];
    // d_in[7] (a2_w), d_in[8] (a2_b): provably no effect on output.

    gat_fused<<<NBLK, NT>>>(x, W1, b1, a1w, a1b, W2, b2, (float*)d_out);
}

// round 5
// speedup vs baseline: 1.0037x; 1.0037x over previous
#include <cuda_runtime.h>

// GAT_28295244546247 — v5: two-kernel graph, NO in-kernel grid sync.
// Analytic collapse (R0): softmax row-constant cancels => identical output rows;
// layer2 softmax exactly uniform; a2_w/a2_b have no effect.
// K1: per-block q/Z partials -> REDG into global accumulators (no fences/spins).
// K2: graph edge = sync; every block redundantly computes the 520-float tail
//     and writes its own output slice; last block resets accumulators.

#define NH    8
#define NBLK  64
#define RPB   64
#define NT    512
#define F_OUT 32

__device__ float    g_q[NH * 64];   // zero-init; K2's last block re-zeroes per replay
__device__ float    g_Z[NH];
__device__ unsigned g_exit = 0;

// ---------------------------------------------------------------- K1
__global__ __launch_bounds__(NT) void gat_k1(
    const float* __restrict__ x,   const float* __restrict__ W1,
    const float* __restrict__ b1,  const float* __restrict__ a1w,
    const float* __restrict__ a1b)
{
    __shared__ float W1s[64 * 65];                  // padded, conflict-free both axes
    __shared__ __align__(16) float a1wjs[NH * 64];  // a1w[:,64:128]
    __shared__ __align__(16) float b1s[64];
    __shared__ __align__(16) float us[NH * 64];     // folded u
    __shared__ float cs[NH];
    __shared__ float xs[RPB * 65];
    __shared__ float es[RPB * NH];
    __shared__ float qs8[8][NH * 64];               // per-l-group partials (no atomics)

    const int t = threadIdx.x;
    const int b = blockIdx.x;
    const int g = t >> 3, u = t & 7;

    // x loads first: latency overlaps staging + fold
    const float4* xr = (const float4*)(x + (b * RPB + g) * 64 + u * 8);
    float4 x0 = xr[0], x1 = xr[1];

    // stage weights (coalesced float4)
    {
        const float4* w4 = (const float4*)W1;
        #pragma unroll
        for (int r = 0; r < 2; r++) {
            int i = t + r * NT;
            float4 v = w4[i];
            int f = i >> 4, k = (i & 15) << 2;
            float* d = &W1s[f * 65 + k];
            d[0] = v.x; d[1] = v.y; d[2] = v.z; d[3] = v.w;
        }
        if (t < 128) {
            int h = t >> 4, q = t & 15;
            ((float4*)a1wjs)[h * 16 + q] = ((const float4*)a1w)[h * 32 + 16 + q];
        } else if (t < 144) {
            ((float4*)b1s)[t - 128] = ((const float4*)b1)[t - 128];
        }
    }
    {
        float* xd = &xs[g * 65 + u * 8];
        xd[0] = x0.x; xd[1] = x0.y; xd[2] = x0.z; xd[3] = x0.w;
        xd[4] = x1.x; xd[5] = x1.y; xd[6] = x1.z; xd[7] = x1.w;
    }
    __syncthreads();

    // fold: u[h][k] = a1wj[h] . W1[:,k]   (1 element/thread)
    {
        const int h = t >> 6, k = t & 63;
        const float* ar = &a1wjs[h * 64];
        float s = 0.f;
        #pragma unroll 16
        for (int f = 0; f < 64; f++) s += ar[f] * W1s[f * 65 + k];
        us[t] = s;
    }
    if (t < NH) {
        float s = a1b[t];
        #pragma unroll 16
        for (int f = 0; f < 64; f++) s += a1wjs[t * 64 + f] * b1s[f];
        cs[t] = s;
    }
    __syncthreads();

    // scores: 8 threads/row, register-resident x, shfl reduce, exp
    {
        float s[NH];
        #pragma unroll
        for (int h = 0; h < NH; h++) {
            float4 u0 = ((const float4*)us)[h * 16 + u * 2];
            float4 u1 = ((const float4*)us)[h * 16 + u * 2 + 1];
            s[h] = u0.x * x0.x + u0.y * x0.y + u0.z * x0.z + u0.w * x0.w
                 + u1.x * x1.x + u1.y * x1.y + u1.z * x1.z + u1.w * x1.w;
        }
        #pragma unroll
        for (int o = 1; o < 8; o <<= 1) {
            #pragma unroll
            for (int h = 0; h < NH; h++)
                s[h] += __shfl_xor_sync(0xffffffffu, s[h], o);
        }
        float sv = s[0];
        #pragma unroll
        for (int h = 1; h < NH; h++) sv = (u == h) ? s[h] : sv;
        es[t] = __expf(sv + cs[u]);             // es[g*8+u]
    }
    __syncthreads();

    // q partial: l-group local accumulation, no atomics
    {
        const int f = t & 63, l = t >> 6;
        float acc[NH];
        #pragma unroll
        for (int h = 0; h < NH; h++) acc[h] = 0.f;
        #pragma unroll
        for (int jj = l; jj < RPB; jj += 8) {
            float xv = xs[jj * 65 + f];
            #pragma unroll
            for (int h = 0; h < NH; h++) acc[h] += es[jj * 8 + h] * xv;
        }
        #pragma unroll
        for (int h = 0; h < NH; h++) qs8[l][h * 64 + f] = acc[h];
    }
    __syncthreads();

    // tree-sum the 8 copies, publish via REDG (no fence: kernel boundary orders)
    {
        float s = 0.f;
        #pragma unroll
        for (int l = 0; l < 8; l++) s += qs8[l][t];
        atomicAdd(&g_q[t], s);
    }
    if (t < NH) {
        float z = 0.f;
        #pragma unroll 16
        for (int jj = 0; jj < RPB; jj++) z += es[jj * 8 + t];
        atomicAdd(&g_Z[t], z);
    }
}

// ---------------------------------------------------------------- K2
__global__ __launch_bounds__(NT) void gat_k2(
    const float* __restrict__ W1, const float* __restrict__ b1,
    const float* __restrict__ W2, const float* __restrict__ b2,
    float* __restrict__ out)
{
    __shared__ float qbar[64];
    __shared__ float os[64];
    __shared__ float fs[F_OUT];
    __shared__ int   s_last;

    const int t = threadIdx.x;
    const int b = blockIdx.x;

    // qbar = (1/NH) * sum_h g_q[h]/g_Z[h]   (L2-broadcast reads)
    if (t < 64) {
        float s = 0.f;
        #pragma unroll
        for (int h = 0; h < NH; h++) s += g_q[h * 64 + t] / g_Z[h];
        qbar[t] = s * (1.f / NH);
    }
    __syncthreads();
    // this block is done reading accumulators -> count arrival for reset
    if (t == 0) s_last = (atomicAdd(&g_exit, 1) == NBLK - 1);

    // m = W1 @ qbar + b1 ; leaky_relu ; elu
    if (t < 64) {
        float s = b1[t];
        const float4* wr = (const float4*)(W1 + t * 64);
        #pragma unroll
        for (int k4 = 0; k4 < 16; k4++) {
            float4 w = wr[k4];
            const float* q4 = &qbar[k4 * 4];
            s += w.x * q4[0] + w.y * q4[1] + w.z * q4[2] + w.w * q4[3];
        }
        float lr = s > 0.f ? s : 0.2f * s;
        os[t] = lr > 0.f ? lr : (__expf(lr) - 1.f);
    }
    __syncthreads();
    // final = leaky_relu(W2 @ os + b2)    (layer2 softmax exactly uniform)
    if (t < F_OUT) {
        float s = b2[t];
        const float4* wr = (const float4*)(W2 + t * 64);
        #pragma unroll
        for (int f4 = 0; f4 < 16; f4++) {
            float4 w = wr[f4];
            const float* o4 = &os[f4 * 4];
            s += w.x * o4[0] + w.y * o4[1] + w.z * o4[2] + w.w * o4[3];
        }
        fs[t] = s > 0.f ? s : 0.2f * s;
    }
    __syncthreads();

    // broadcast final row to this block's 64 output rows (1 float4/thread)
    {
        int f0 = (t & 7) << 2;
        float4 v = make_float4(fs[f0], fs[f0 + 1], fs[f0 + 2], fs[f0 + 3]);
        ((float4*)out)[b * NT + t] = v;
    }

    // last block (all blocks have read g_q/g_Z by now) resets for next replay
    if (s_last) {
        g_q[t] = 0.f;
        if (t < NH) g_Z[t] = 0.f;
        if (t == 0) g_exit = 0;
    }
}

extern "C" void kernel_launch(void* const* d_in, const int* in_sizes, int n_in,
                              void* d_out, int out_size) {
    const float* x   = (const float*)d_in[0];
    const float* W1  = (const float*)d_in[1];
    const float* b1  = (const float*)d_in[2];
    const float* a1w = (const float*)d_in[3];
    const float* a1b = (const float*)d_in[4];
    const float* W2  = (const float*)d_in[5];
    const float* b2  = (const float*)d_in[6];
    // d_in[7] (a2_w), d_in[8] (a2_b): provably no effect on output.

    gat_k1<<<NBLK, NT>>>(x, W1, b1, a1w, a1b);
    gat_k2<<<NBLK, NT>>>(W1, b1, W2, b2, (float*)d_out);
}

// round 6
// speedup vs baseline: 1.3170x; 1.3120x over previous
#include <cuda_runtime.h>

// GAT_28295244546247 — v6: two-kernel graph, K2 rebuilt for minimal
// dependent-latency chains (all 512 threads in every phase, shfl reductions).
// Analytic collapse (R0): softmax row-constant cancels => identical output rows;
// layer2 softmax exactly uniform; a2_w/a2_b have no effect.

#define NH    8
#define NBLK  64
#define RPB   64
#define NT    512
#define F_OUT 32

__device__ float    g_q[NH * 64];   // zero-init; K2's last block re-zeroes per replay
__device__ float    g_Z[NH];
__device__ unsigned g_exit = 0;

// ---------------------------------------------------------------- K1
__global__ __launch_bounds__(NT) void gat_k1(
    const float* __restrict__ x,   const float* __restrict__ W1,
    const float* __restrict__ b1,  const float* __restrict__ a1w,
    const float* __restrict__ a1b)
{
    __shared__ float W1s[64 * 65];                  // padded, conflict-free both axes
    __shared__ __align__(16) float a1wjs[NH * 64];  // a1w[:,64:128]
    __shared__ __align__(16) float b1s[64];
    __shared__ __align__(16) float us[NH * 64];     // folded u
    __shared__ float cs[NH];
    __shared__ float xs[RPB * 65];
    __shared__ float es[RPB * NH];
    __shared__ float qs8[8][NH * 64];               // per-l-group partials (no atomics)

    const int t = threadIdx.x;
    const int b = blockIdx.x;
    const int g = t >> 3, u = t & 7;

    // x loads first: latency overlaps staging + fold
    const float4* xr = (const float4*)(x + (b * RPB + g) * 64 + u * 8);
    float4 x0 = xr[0], x1 = xr[1];

    // stage weights (coalesced float4)
    {
        const float4* w4 = (const float4*)W1;
        #pragma unroll
        for (int r = 0; r < 2; r++) {
            int i = t + r * NT;
            float4 v = w4[i];
            int f = i >> 4, k = (i & 15) << 2;
            float* d = &W1s[f * 65 + k];
            d[0] = v.x; d[1] = v.y; d[2] = v.z; d[3] = v.w;
        }
        if (t < 128) {
            int h = t >> 4, q = t & 15;
            ((float4*)a1wjs)[h * 16 + q] = ((const float4*)a1w)[h * 32 + 16 + q];
        } else if (t < 144) {
            ((float4*)b1s)[t - 128] = ((const float4*)b1)[t - 128];
        }
    }
    {
        float* xd = &xs[g * 65 + u * 8];
        xd[0] = x0.x; xd[1] = x0.y; xd[2] = x0.z; xd[3] = x0.w;
        xd[4] = x1.x; xd[5] = x1.y; xd[6] = x1.z; xd[7] = x1.w;
    }
    __syncthreads();

    // fold: u[h][k] = a1wj[h] . W1[:,k]   (1 element/thread)
    {
        const int h = t >> 6, k = t & 63;
        const float* ar = &a1wjs[h * 64];
        float s = 0.f;
        #pragma unroll 16
        for (int f = 0; f < 64; f++) s += ar[f] * W1s[f * 65 + k];
        us[t] = s;
    }
    if (t < NH) {
        float s = a1b[t];
        #pragma unroll 16
        for (int f = 0; f < 64; f++) s += a1wjs[t * 64 + f] * b1s[f];
        cs[t] = s;
    }
    __syncthreads();

    // scores: 8 threads/row, register-resident x, shfl reduce, exp
    {
        float s[NH];
        #pragma unroll
        for (int h = 0; h < NH; h++) {
            float4 u0 = ((const float4*)us)[h * 16 + u * 2];
            float4 u1 = ((const float4*)us)[h * 16 + u * 2 + 1];
            s[h] = u0.x * x0.x + u0.y * x0.y + u0.z * x0.z + u0.w * x0.w
                 + u1.x * x1.x + u1.y * x1.y + u1.z * x1.z + u1.w * x1.w;
        }
        #pragma unroll
        for (int o = 1; o < 8; o <<= 1) {
            #pragma unroll
            for (int h = 0; h < NH; h++)
                s[h] += __shfl_xor_sync(0xffffffffu, s[h], o);
        }
        float sv = s[0];
        #pragma unroll
        for (int h = 1; h < NH; h++) sv = (u == h) ? s[h] : sv;
        es[t] = __expf(sv + cs[u]);             // es[g*8+u]
    }
    __syncthreads();

    // q partial: l-group local accumulation, no atomics
    {
        const int f = t & 63, l = t >> 6;
        float acc[NH];
        #pragma unroll
        for (int h = 0; h < NH; h++) acc[h] = 0.f;
        #pragma unroll
        for (int jj = l; jj < RPB; jj += 8) {
            float xv = xs[jj * 65 + f];
            #pragma unroll
            for (int h = 0; h < NH; h++) acc[h] += es[jj * 8 + h] * xv;
        }
        #pragma unroll
        for (int h = 0; h < NH; h++) qs8[l][h * 64 + f] = acc[h];
    }
    __syncthreads();

    // tree-sum the 8 copies, publish via REDG (kernel boundary orders visibility)
    {
        float s = 0.f;
        #pragma unroll
        for (int l = 0; l < 8; l++) s += qs8[l][t];
        atomicAdd(&g_q[t], s);
    }
    if (t < NH) {
        float z = 0.f;
        #pragma unroll 16
        for (int jj = 0; jj < RPB; jj++) z += es[jj * 8 + t];
        atomicAdd(&g_Z[t], z);
    }
}

// ---------------------------------------------------------------- K2
// All 512 threads in every phase; dependent chains = 1 load + shfl tree.
__global__ __launch_bounds__(NT) void gat_k2(
    const float* __restrict__ W1, const float* __restrict__ b1,
    const float* __restrict__ W2, const float* __restrict__ b2,
    float* __restrict__ out)
{
    __shared__ float qbar[64];
    __shared__ float os[64];
    __shared__ float fs[F_OUT];
    __shared__ int   s_last;

    const int t = threadIdx.x;
    const int b = blockIdx.x;

    // ---- qbar[f] = (1/NH) sum_h g_q[h][f]/g_Z[h]
    //      t = f*8 + h : one LDG pair per thread, 3-round shfl over h ----
    {
        const int f = t >> 3, h = t & 7;
        float v = g_q[h * 64 + f] / g_Z[h];
        v += __shfl_xor_sync(0xffffffffu, v, 1);
        v += __shfl_xor_sync(0xffffffffu, v, 2);
        v += __shfl_xor_sync(0xffffffffu, v, 4);
        if (h == 0) qbar[f] = v * (1.f / NH);
    }
    __syncthreads();
    if (t == 0) s_last = (atomicAdd(&g_exit, 1) == NBLK - 1);  // g_q consumed

    // ---- os[m] = elu(lrelu(W1[m,:].qbar + b1[m])) : 8 threads per output ----
    {
        const int m = t >> 3, kc = t & 7;                    // kc: 8-float chunk
        const float4* wr = (const float4*)(W1 + m * 64 + kc * 8);
        float4 w0 = wr[0], w1 = wr[1];
        const float* q8 = &qbar[kc * 8];
        float s = w0.x * q8[0] + w0.y * q8[1] + w0.z * q8[2] + w0.w * q8[3]
                + w1.x * q8[4] + w1.y * q8[5] + w1.z * q8[6] + w1.w * q8[7];
        s += __shfl_xor_sync(0xffffffffu, s, 1);
        s += __shfl_xor_sync(0xffffffffu, s, 2);
        s += __shfl_xor_sync(0xffffffffu, s, 4);
        if (kc == 0) {
            s += b1[m];
            float lr = s > 0.f ? s : 0.2f * s;
            os[m] = lr > 0.f ? lr : (__expf(lr) - 1.f);
        }
    }
    __syncthreads();

    // ---- fs[m] = lrelu(W2[m,:].os + b2[m]) : 16 threads per output ----
    {
        const int m = t >> 4, kc = t & 15;                   // kc: 4-float chunk
        float4 w = ((const float4*)(W2 + m * 64))[kc];
        const float* o4 = &os[kc * 4];
        float s = w.x * o4[0] + w.y * o4[1] + w.z * o4[2] + w.w * o4[3];
        s += __shfl_xor_sync(0xffffffffu, s, 1);
        s += __shfl_xor_sync(0xffffffffu, s, 2);
        s += __shfl_xor_sync(0xffffffffu, s, 4);
        s += __shfl_xor_sync(0xffffffffu, s, 8);
        if (kc == 0) {
            s += b2[m];
            fs[m] = s > 0.f ? s : 0.2f * s;
        }
    }
    __syncthreads();

    // ---- broadcast final row to this block's 64 output rows (1 float4/thread) ----
    {
        int f0 = (t & 7) << 2;
        float4 v = make_float4(fs[f0], fs[f0 + 1], fs[f0 + 2], fs[f0 + 3]);
        ((float4*)out)[b * NT + t] = v;
    }

    // ---- last block (all blocks have read g_q/g_Z) resets for next replay ----
    if (s_last) {
        g_q[t] = 0.f;
        if (t < NH) g_Z[t] = 0.f;
        if (t == 0) g_exit = 0;
    }
}

extern "C" void kernel_launch(void* const* d_in, const int* in_sizes, int n_in,
                              void* d_out, int out_size) {
    const float* x   = (const float*)d_in[0];
    const float* W1  = (const float*)d_in[1];
    const float* b1  = (const float*)d_in[2];
    const float* a1w = (const float*)d_in[3];
    const float* a1b = (const float*)d_in[4];
    const float* W2  = (const float*)d_in[5];
    const float* b2  = (const float*)d_in[6];
    // d_in[7] (a2_w), d_in[8] (a2_b): provably no effect on output.

    gat_k1<<<NBLK, NT>>>(x, W1, b1, a1w, a1b);
    gat_k2<<<NBLK, NT>>>(W1, b1, W2, b2, (float*)d_out);
}

// round 7
// speedup vs baseline: 1.3434x; 1.0201x over previous
#include <cuda_runtime.h>

// GAT_28295244546247 — v7: single fused kernel with lean (shfl-based) tail.
// Analytic collapse (R0): softmax row-constant cancels => identical output rows;
// layer2 softmax exactly uniform; a2_w/a2_b have no effect.
// Model (R6): time = launch overhead + sum of longest dependent chains.
// v7 = v6's K1 (acc-split fold) + v6's chain-lean K2 tail, fused with the
// R3-validated fence/arrive/poll grid sync (measured cost ~= 0 in R5).

#define NH    8
#define NBLK  64
#define RPB   64
#define NT    512
#define F_OUT 32

__device__ float    g_q[NH * 64];   // zero-init; reset by last exiter each replay
__device__ float    g_Z[NH];
__device__ unsigned g_arrive = 0;
__device__ unsigned g_exit   = 0;

__global__ __launch_bounds__(NT) void gat_fused(
    const float* __restrict__ x,   const float* __restrict__ W1,
    const float* __restrict__ b1,  const float* __restrict__ a1w,
    const float* __restrict__ a1b, const float* __restrict__ W2,
    const float* __restrict__ b2,  float* __restrict__ out)
{
    __shared__ float W1s[64 * 65];                  // padded, conflict-free both axes
    __shared__ __align__(16) float a1wjs[NH * 64];  // a1w[:,64:128]
    __shared__ __align__(16) float b1s[64];
    __shared__ __align__(16) float us[NH * 64];     // folded u
    __shared__ float cs[NH];
    __shared__ float xs[RPB * 65];
    __shared__ float es[RPB * NH];
    __shared__ float qs8[8][NH * 64];               // per-l-group partials
    __shared__ float qbar[64];
    __shared__ float os[64];
    __shared__ float fs[F_OUT];
    __shared__ int   s_last;

    const int t = threadIdx.x;
    const int b = blockIdx.x;
    const int g = t >> 3, u = t & 7;

    // ---- x loads first: latency overlaps staging + fold ----
    const float4* xr = (const float4*)(x + (b * RPB + g) * 64 + u * 8);
    float4 x0 = xr[0], x1 = xr[1];

    // ---- stage weights (coalesced float4) ----
    {
        const float4* w4 = (const float4*)W1;
        #pragma unroll
        for (int r = 0; r < 2; r++) {
            int i = t + r * NT;
            float4 v = w4[i];
            int f = i >> 4, k = (i & 15) << 2;
            float* d = &W1s[f * 65 + k];
            d[0] = v.x; d[1] = v.y; d[2] = v.z; d[3] = v.w;
        }
        if (t < 128) {
            int h = t >> 4, q = t & 15;
            ((float4*)a1wjs)[h * 16 + q] = ((const float4*)a1w)[h * 32 + 16 + q];
        } else if (t < 144) {
            ((float4*)b1s)[t - 128] = ((const float4*)b1)[t - 128];
        }
    }
    {
        float* xd = &xs[g * 65 + u * 8];
        xd[0] = x0.x; xd[1] = x0.y; xd[2] = x0.z; xd[3] = x0.w;
        xd[4] = x1.x; xd[5] = x1.y; xd[6] = x1.z; xd[7] = x1.w;
    }
    __syncthreads();

    // ---- fold: u[h][k] = a1wj[h] . W1[:,k]  (4-way acc split: chain 64->16) ----
    {
        const int h = t >> 6, k = t & 63;
        const float* ar = &a1wjs[h * 64];
        float s0 = 0.f, s1 = 0.f, s2 = 0.f, s3 = 0.f;
        #pragma unroll
        for (int f = 0; f < 64; f += 4) {
            s0 += ar[f + 0] * W1s[(f + 0) * 65 + k];
            s1 += ar[f + 1] * W1s[(f + 1) * 65 + k];
            s2 += ar[f + 2] * W1s[(f + 2) * 65 + k];
            s3 += ar[f + 3] * W1s[(f + 3) * 65 + k];
        }
        us[t] = (s0 + s1) + (s2 + s3);
    }
    if (t < NH) {
        const float* ar = &a1wjs[t * 64];
        float s0 = 0.f, s1 = 0.f, s2 = 0.f, s3 = 0.f;
        #pragma unroll
        for (int f = 0; f < 64; f += 4) {
            s0 += ar[f + 0] * b1s[f + 0];
            s1 += ar[f + 1] * b1s[f + 1];
            s2 += ar[f + 2] * b1s[f + 2];
            s3 += ar[f + 3] * b1s[f + 3];
        }
        cs[t] = a1b[t] + (s0 + s1) + (s2 + s3);
    }
    __syncthreads();

    // ---- scores: 8 threads/row, register-resident x, shfl reduce, exp ----
    {
        float s[NH];
        #pragma unroll
        for (int h = 0; h < NH; h++) {
            float4 u0 = ((const float4*)us)[h * 16 + u * 2];
            float4 u1 = ((const float4*)us)[h * 16 + u * 2 + 1];
            s[h] = u0.x * x0.x + u0.y * x0.y + u0.z * x0.z + u0.w * x0.w
                 + u1.x * x1.x + u1.y * x1.y + u1.z * x1.z + u1.w * x1.w;
        }
        #pragma unroll
        for (int o = 1; o < 8; o <<= 1) {
            #pragma unroll
            for (int h = 0; h < NH; h++)
                s[h] += __shfl_xor_sync(0xffffffffu, s[h], o);
        }
        float sv = s[0];
        #pragma unroll
        for (int h = 1; h < NH; h++) sv = (u == h) ? s[h] : sv;
        es[t] = __expf(sv + cs[u]);             // es[g*8+u]
    }
    __syncthreads();

    // ---- q partial: l-group local accumulation (no atomics) ----
    {
        const int f = t & 63, l = t >> 6;
        float acc[NH];
        #pragma unroll
        for (int h = 0; h < NH; h++) acc[h] = 0.f;
        #pragma unroll
        for (int jj = l; jj < RPB; jj += 8) {
            float xv = xs[jj * 65 + f];
            #pragma unroll
            for (int h = 0; h < NH; h++) acc[h] += es[jj * 8 + h] * xv;
        }
        #pragma unroll
        for (int h = 0; h < NH; h++) qs8[l][h * 64 + f] = acc[h];
    }
    __syncthreads();

    // ---- tree-sum copies, publish via REDG ----
    {
        float s = 0.f;
        #pragma unroll
        for (int l = 0; l < 8; l++) s += qs8[l][t];
        atomicAdd(&g_q[t], s);
    }
    if (t < NH) {
        float z0 = 0.f, z1 = 0.f, z2 = 0.f, z3 = 0.f;
        #pragma unroll
        for (int jj = 0; jj < RPB; jj += 4) {
            z0 += es[(jj + 0) * 8 + t];
            z1 += es[(jj + 1) * 8 + t];
            z2 += es[(jj + 2) * 8 + t];
            z3 += es[(jj + 3) * 8 + t];
        }
        atomicAdd(&g_Z[t], (z0 + z1) + (z2 + z3));
    }

    // ---- grid sync (R3-validated; measured ~free in R5) ----
    __threadfence();
    __syncthreads();
    if (t == 0) {
        atomicAdd(&g_arrive, 1);
        while (*(volatile unsigned*)&g_arrive < NBLK) __nanosleep(32);
    }
    __syncthreads();
    __threadfence();

    // ---- lean tail (R6 structure): 1 LDG + shfl tree per phase ----
    // qbar[f] = (1/NH) sum_h g_q[h][f]/g_Z[h];  t = f*8 + h
    {
        const int f = t >> 3, h = t & 7;
        float v = g_q[h * 64 + f] / g_Z[h];
        v += __shfl_xor_sync(0xffffffffu, v, 1);
        v += __shfl_xor_sync(0xffffffffu, v, 2);
        v += __shfl_xor_sync(0xffffffffu, v, 4);
        if (h == 0) qbar[f] = v * (1.f / NH);
    }
    __syncthreads();

    // os[m] = elu(lrelu(W1s[m,:].qbar + b1[m])) : 8 threads per output (smem W1)
    {
        const int m = t >> 3, kc = t & 7;
        const float* wr = &W1s[m * 65 + kc * 8];
        const float* q8 = &qbar[kc * 8];
        float s = wr[0] * q8[0] + wr[1] * q8[1] + wr[2] * q8[2] + wr[3] * q8[3]
                + wr[4] * q8[4] + wr[5] * q8[5] + wr[6] * q8[6] + wr[7] * q8[7];
        s += __shfl_xor_sync(0xffffffffu, s, 1);
        s += __shfl_xor_sync(0xffffffffu, s, 2);
        s += __shfl_xor_sync(0xffffffffu, s, 4);
        if (kc == 0) {
            s += b1s[m];
            float lr = s > 0.f ? s : 0.2f * s;
            os[m] = lr > 0.f ? lr : (__expf(lr) - 1.f);
        }
    }
    __syncthreads();

    // fs[m] = lrelu(W2[m,:].os + b2[m]) : 16 threads per output
    {
        const int m = t >> 4, kc = t & 15;
        float4 w = ((const float4*)(W2 + m * 64))[kc];
        const float* o4 = &os[kc * 4];
        float s = w.x * o4[0] + w.y * o4[1] + w.z * o4[2] + w.w * o4[3];
        s += __shfl_xor_sync(0xffffffffu, s, 1);
        s += __shfl_xor_sync(0xffffffffu, s, 2);
        s += __shfl_xor_sync(0xffffffffu, s, 4);
        s += __shfl_xor_sync(0xffffffffu, s, 8);
        if (kc == 0) {
            s += b2[m];
            fs[m] = s > 0.f ? s : 0.2f * s;
        }
    }
    __syncthreads();

    // ---- broadcast final row to this block's 64 output rows ----
    {
        int f0 = (t & 7) << 2;
        float4 v = make_float4(fs[f0], fs[f0 + 1], fs[f0 + 2], fs[f0 + 3]);
        ((float4*)out)[b * NT + t] = v;
    }

    // ---- reset for next graph replay (last exiting block; all reads done) ----
    __syncthreads();
    if (t == 0) s_last = (atomicAdd(&g_exit, 1) == NBLK - 1);
    __syncthreads();
    if (s_last) {
        g_q[t] = 0.f;
        if (t < NH) g_Z[t] = 0.f;
        if (t == 0) { g_arrive = 0; g_exit = 0; }
    }
}

extern "C" void kernel_launch(void* const* d_in, const int* in_sizes, int n_in,
                              void* d_out, int out_size) {
    const float* x   = (const float*)d_in[0];
    const float* W1  = (const float*)d_in[1];
    const float* b1  = (const float*)d_in[2];
    const float* a1w = (const float*)d_in[3];
    const float* a1b = (const float*)d_in[4];
    const float* W2  = (const float*)d_in[5];
    const float* b2  = (const float*)d_in[6];
    // d_in[7] (a2_w), d_in[8] (a2_b): provably no effect on output.

    gat_fused<<<NBLK, NT>>>(x, W1, b1, a1w, a1b, W2, b2, (float*)d_out);
}

// round 8
// speedup vs baseline: 1.3850x; 1.0310x over previous
#include <cuda_runtime.h>

// GAT_28295244546247 — v8: fused kernel, smem-wavefront-optimized.
// Analytic collapse (R0): softmax row-constant cancels => identical output rows;
// layer2 softmax exactly uniform; a2_w/a2_b have no effect.
// v8: fold v2 (W1s read once, shared across 8 heads), NBLK=128/RPB=32
//     (halve per-block score/q work), float4 es reads, W2 staged in poll window.

#define NH    8
#define NBLK  128
#define RPB   32
#define NT    512
#define F_OUT 32

__device__ float    g_q[NH * 64];   // zero-init; reset by last exiter each replay
__device__ float    g_Z[NH];
__device__ unsigned g_arrive = 0;
__device__ unsigned g_exit   = 0;

__global__ __launch_bounds__(NT) void gat_fused(
    const float* __restrict__ x,   const float* __restrict__ W1,
    const float* __restrict__ b1,  const float* __restrict__ a1w,
    const float* __restrict__ a1b, const float* __restrict__ W2,
    const float* __restrict__ b2,  float* __restrict__ out)
{
    __shared__ float W1s[64 * 65];                  // padded, conflict-free both axes
    __shared__ __align__(16) float W2s[F_OUT * 64];
    __shared__ __align__(16) float a1wjs[NH * 64];  // a1w[:,64:128]
    __shared__ __align__(16) float b1s[64];
    __shared__ __align__(16) float b2s[F_OUT];
    __shared__ __align__(16) float us[NH * 64];     // folded u [h][k]
    __shared__ float cs[NH];
    __shared__ __align__(16) float xs[RPB * 68];    // stride 68: float4-aligned rows
    __shared__ __align__(16) float es[RPB * NH];
    __shared__ float qs8[8][NH * 64];               // 8-copy partials (fold & q-accum)
    __shared__ float qbar[64];
    __shared__ float os[64];
    __shared__ float fs[F_OUT];
    __shared__ int   s_last;

    const int t = threadIdx.x;
    const int b = blockIdx.x;
    const int g = t >> 4, u = t & 15;               // 32 rows x 16 threads/row

    // ---- phase 0: x load (1 float4/thread) + weight staging ----
    float4 x4 = ((const float4*)(x + (b * RPB + g) * 64 + u * 4))[0];
    {
        const float4* w4 = (const float4*)W1;
        #pragma unroll
        for (int r = 0; r < 2; r++) {
            int i = t + r * NT;
            float4 v = w4[i];
            int f = i >> 4, k = (i & 15) << 2;
            float* d = &W1s[f * 65 + k];
            d[0] = v.x; d[1] = v.y; d[2] = v.z; d[3] = v.w;
        }
        if (t < 128) {
            int h = t >> 4, q = t & 15;
            ((float4*)a1wjs)[h * 16 + q] = ((const float4*)a1w)[h * 32 + 16 + q];
        } else if (t < 144) {
            ((float4*)b1s)[t - 128] = ((const float4*)b1)[t - 128];
        }
        ((float4*)&xs[g * 68])[u] = x4;
    }
    __syncthreads();

    // ---- phase 1: fold v2 — each W1s value read ONCE, shared across 8 heads ----
    // t = fg*64 + k (fg: 8-f group, k: output column). acc[h] += W1[f][k]*ar[h][f]
    {
        const int fg = t >> 6, k = t & 63;
        float acc[NH];
        #pragma unroll
        for (int h = 0; h < NH; h++) acc[h] = 0.f;
        #pragma unroll
        for (int q = 0; q < 2; q++) {               // two f-quads
            const int f0 = fg * 8 + q * 4;
            float4 ar[NH];                           // broadcast LDS.128 per head
            #pragma unroll
            for (int h = 0; h < NH; h++)
                ar[h] = ((const float4*)&a1wjs[h * 64 + f0])[0];
            #pragma unroll
            for (int fo = 0; fo < 4; fo++) {
                float w = W1s[(f0 + fo) * 65 + k];
                #pragma unroll
                for (int h = 0; h < NH; h++) {
                    float a = (fo == 0) ? ar[h].x : (fo == 1) ? ar[h].y
                            : (fo == 2) ? ar[h].z : ar[h].w;
                    acc[h] += w * a;
                }
            }
        }
        #pragma unroll
        for (int h = 0; h < NH; h++) qs8[fg][h * 64 + k] = acc[h];
    }
    if (t < NH) {                                    // c[h] = a1b + ar.b1 (4-acc)
        const float* ar = &a1wjs[t * 64];
        float s0 = 0.f, s1 = 0.f, s2 = 0.f, s3 = 0.f;
        #pragma unroll
        for (int f = 0; f < 64; f += 4) {
            s0 += ar[f + 0] * b1s[f + 0];
            s1 += ar[f + 1] * b1s[f + 1];
            s2 += ar[f + 2] * b1s[f + 2];
            s3 += ar[f + 3] * b1s[f + 3];
        }
        cs[t] = a1b[t] + (s0 + s1) + (s2 + s3);
    }
    __syncthreads();

    // ---- phase 2: tree-sum fold partials -> us ----
    {
        float s0 = 0.f, s1 = 0.f;
        #pragma unroll
        for (int c = 0; c < 8; c += 2) { s0 += qs8[c][t]; s1 += qs8[c + 1][t]; }
        us[t] = s0 + s1;
    }
    __syncthreads();

    // ---- phase 3: scores — 16 threads/row, 4-round shfl, exp ----
    {
        float s[NH];
        #pragma unroll
        for (int h = 0; h < NH; h++) {
            float4 u4 = ((const float4*)us)[h * 16 + u];
            s[h] = u4.x * x4.x + u4.y * x4.y + u4.z * x4.z + u4.w * x4.w;
        }
        #pragma unroll
        for (int o = 1; o < 16; o <<= 1) {
            #pragma unroll
            for (int h = 0; h < NH; h++)
                s[h] += __shfl_xor_sync(0xffffffffu, s[h], o);
        }
        if (u < NH) {
            float sv = s[0];
            #pragma unroll
            for (int h = 1; h < NH; h++) sv = (u == h) ? s[h] : sv;
            es[g * 8 + u] = __expf(sv + cs[u]);
        }
    }
    __syncthreads();

    // ---- phase 4: q partial (f-parallel, 8 j-lanes, float4 es reads) ----
    {
        const int f = t & 63, l = t >> 6;
        float acc[NH];
        #pragma unroll
        for (int h = 0; h < NH; h++) acc[h] = 0.f;
        #pragma unroll
        for (int jj = l; jj < RPB; jj += 8) {
            float4 e0 = ((const float4*)&es[jj * 8])[0];
            float4 e1 = ((const float4*)&es[jj * 8])[1];
            float xv = xs[jj * 68 + f];
            acc[0] += e0.x * xv; acc[1] += e0.y * xv;
            acc[2] += e0.z * xv; acc[3] += e0.w * xv;
            acc[4] += e1.x * xv; acc[5] += e1.y * xv;
            acc[6] += e1.z * xv; acc[7] += e1.w * xv;
        }
        #pragma unroll
        for (int h = 0; h < NH; h++) qs8[l][h * 64 + f] = acc[h];
    }
    __syncthreads();

    // ---- phase 5: tree-sum + REDG publish ----
    {
        float s0 = 0.f, s1 = 0.f;
        #pragma unroll
        for (int c = 0; c < 8; c += 2) { s0 += qs8[c][t]; s1 += qs8[c + 1][t]; }
        atomicAdd(&g_q[t], s0 + s1);
    }
    if (t < NH) {
        float z0 = 0.f, z1 = 0.f, z2 = 0.f, z3 = 0.f;
        #pragma unroll
        for (int jj = 0; jj < RPB; jj += 4) {
            z0 += es[(jj + 0) * 8 + t];
            z1 += es[(jj + 1) * 8 + t];
            z2 += es[(jj + 2) * 8 + t];
            z3 += es[(jj + 3) * 8 + t];
        }
        atomicAdd(&g_Z[t], (z0 + z1) + (z2 + z3));
    }

    // ---- grid sync; stage W2/b2 inside the poll window ----
    __threadfence();
    __syncthreads();
    if (t == 0) atomicAdd(&g_arrive, 1);
    ((float4*)W2s)[t] = ((const float4*)W2)[t];
    if (t < NH) ((float4*)b2s)[t] = ((const float4*)b2)[t];
    if (t == 0) {
        while (*(volatile unsigned*)&g_arrive < NBLK) __nanosleep(32);
    }
    __syncthreads();
    __threadfence();

    // ---- tail (R6 lean structure) ----
    {
        const int f = t >> 3, h = t & 7;
        float v = g_q[h * 64 + f] / g_Z[h];
        v += __shfl_xor_sync(0xffffffffu, v, 1);
        v += __shfl_xor_sync(0xffffffffu, v, 2);
        v += __shfl_xor_sync(0xffffffffu, v, 4);
        if (h == 0) qbar[f] = v * (1.f / NH);
    }
    __syncthreads();
    if (t == 0) s_last = (atomicAdd(&g_exit, 1) == NBLK - 1);  // g_q consumed

    {   // os[m] = elu(lrelu(W1s[m,:].qbar + b1[m])) : 8 threads/output
        const int m = t >> 3, kc = t & 7;
        const float* wr = &W1s[m * 65 + kc * 8];
        const float* q8 = &qbar[kc * 8];
        float s = wr[0] * q8[0] + wr[1] * q8[1] + wr[2] * q8[2] + wr[3] * q8[3]
                + wr[4] * q8[4] + wr[5] * q8[5] + wr[6] * q8[6] + wr[7] * q8[7];
        s += __shfl_xor_sync(0xffffffffu, s, 1);
        s += __shfl_xor_sync(0xffffffffu, s, 2);
        s += __shfl_xor_sync(0xffffffffu, s, 4);
        if (kc == 0) {
            s += b1s[m];
            float lr = s > 0.f ? s : 0.2f * s;
            os[m] = lr > 0.f ? lr : (__expf(lr) - 1.f);
        }
    }
    __syncthreads();
    {   // fs[m] = lrelu(W2s[m,:].os + b2[m]) : 16 threads/output
        const int m = t >> 4, kc = t & 15;
        float4 w = ((const float4*)W2s)[m * 16 + kc];
        const float* o4 = &os[kc * 4];
        float s = w.x * o4[0] + w.y * o4[1] + w.z * o4[2] + w.w * o4[3];
        s += __shfl_xor_sync(0xffffffffu, s, 1);
        s += __shfl_xor_sync(0xffffffffu, s, 2);
        s += __shfl_xor_sync(0xffffffffu, s, 4);
        s += __shfl_xor_sync(0xffffffffu, s, 8);
        if (kc == 0) {
            s += b2s[m];
            fs[m] = s > 0.f ? s : 0.2f * s;
        }
    }
    __syncthreads();

    // ---- output: 32 rows x 32 cols per block = 256 float4 ----
    if (t < 256) {
        int f0 = (t & 7) << 2;
        float4 v = make_float4(fs[f0], fs[f0 + 1], fs[f0 + 2], fs[f0 + 3]);
        ((float4*)out)[b * 256 + t] = v;
    }

    // ---- reset for next graph replay (last exiting block; all reads done) ----
    __syncthreads();
    if (s_last) {
        g_q[t] = 0.f;
        if (t < NH) g_Z[t] = 0.f;
        if (t == 0) { g_arrive = 0; g_exit = 0; }
    }
}

extern "C" void kernel_launch(void* const* d_in, const int* in_sizes, int n_in,
                              void* d_out, int out_size) {
    const float* x   = (const float*)d_in[0];
    const float* W1  = (const float*)d_in[1];
    const float* b1  = (const float*)d_in[2];
    const float* a1w = (const float*)d_in[3];
    const float* a1b = (const float*)d_in[4];
    const float* W2  = (const float*)d_in[5];
    const float* b2  = (const float*)d_in[6];
    // d_in[7] (a2_w), d_in[8] (a2_b): provably no effect on output.

    gat_fused<<<NBLK, NT>>>(x, W1, b1, a1w, a1b, W2, b2, (float*)d_out);
}

// round 9
// speedup vs baseline: 1.5952x; 1.1518x over previous
#include <cuda_runtime.h>

// GAT_28295244546247 — v8: fused kernel, smem-wavefront-optimized.
// Analytic collapse (R0): softmax row-constant cancels => identical output rows;
// layer2 softmax exactly uniform; a2_w/a2_b have no effect.
// v8: fold v2 (W1s read once, shared across 8 heads), NBLK=128/RPB=32
//     (halve per-block score/q work), float4 es reads, W2 staged in poll window.

#define NH    8
#define NBLK  128
#define RPB   32
#define NT    512
#define F_OUT 32

__device__ float    g_q[NH * 64];   // zero-init; reset by last exiter each replay
__device__ float    g_Z[NH];
__device__ unsigned g_arrive = 0;
__device__ unsigned g_exit   = 0;

__global__ __launch_bounds__(NT) void gat_fused(
    const float* __restrict__ x,   const float* __restrict__ W1,
    const float* __restrict__ b1,  const float* __restrict__ a1w,
    const float* __restrict__ a1b, const float* __restrict__ W2,
    const float* __restrict__ b2,  float* __restrict__ out)
{
    __shared__ float W1s[64 * 65];                  // padded, conflict-free both axes
    __shared__ __align__(16) float W2s[F_OUT * 64];
    __shared__ __align__(16) float a1wjs[NH * 64];  // a1w[:,64:128]
    __shared__ __align__(16) float b1s[64];
    __shared__ __align__(16) float b2s[F_OUT];
    __shared__ __align__(16) float us[NH * 64];     // folded u [h][k]
    __shared__ float cs[NH];
    __shared__ __align__(16) float xs[RPB * 68];    // stride 68: float4-aligned rows
    __shared__ __align__(16) float es[RPB * NH];
    __shared__ float qs8[8][NH * 64];               // 8-copy partials (fold & q-accum)
    __shared__ float qbar[64];
    __shared__ float os[64];
    __shared__ float fs[F_OUT];
    __shared__ int   s_last;

    const int t = threadIdx.x;
    const int b = blockIdx.x;
    const int g = t >> 4, u = t & 15;               // 32 rows x 16 threads/row

    // ---- phase 0: x load (1 float4/thread) + weight staging ----
    float4 x4 = ((const float4*)(x + (b * RPB + g) * 64 + u * 4))[0];
    {
        const float4* w4 = (const float4*)W1;
        #pragma unroll
        for (int r = 0; r < 2; r++) {
            int i = t + r * NT;
            float4 v = w4[i];
            int f = i >> 4, k = (i & 15) << 2;
            float* d = &W1s[f * 65 + k];
            d[0] = v.x; d[1] = v.y; d[2] = v.z; d[3] = v.w;
        }
        if (t < 128) {
            int h = t >> 4, q = t & 15;
            ((float4*)a1wjs)[h * 16 + q] = ((const float4*)a1w)[h * 32 + 16 + q];
        } else if (t < 144) {
            ((float4*)b1s)[t - 128] = ((const float4*)b1)[t - 128];
        }
        ((float4*)&xs[g * 68])[u] = x4;
    }
    __syncthreads();

    // ---- phase 1: fold v2 — each W1s value read ONCE, shared across 8 heads ----
    // t = fg*64 + k (fg: 8-f group, k: output column). acc[h] += W1[f][k]*ar[h][f]
    {
        const int fg = t >> 6, k = t & 63;
        float acc[NH];
        #pragma unroll
        for (int h = 0; h < NH; h++) acc[h] = 0.f;
        #pragma unroll
        for (int q = 0; q < 2; q++) {               // two f-quads
            const int f0 = fg * 8 + q * 4;
            float4 ar[NH];                           // broadcast LDS.128 per head
            #pragma unroll
            for (int h = 0; h < NH; h++)
                ar[h] = ((const float4*)&a1wjs[h * 64 + f0])[0];
            #pragma unroll
            for (int fo = 0; fo < 4; fo++) {
                float w = W1s[(f0 + fo) * 65 + k];
                #pragma unroll
                for (int h = 0; h < NH; h++) {
                    float a = (fo == 0) ? ar[h].x : (fo == 1) ? ar[h].y
                            : (fo == 2) ? ar[h].z : ar[h].w;
                    acc[h] += w * a;
                }
            }
        }
        #pragma unroll
        for (int h = 0; h < NH; h++) qs8[fg][h * 64 + k] = acc[h];
    }
    if (t < NH) {                                    // c[h] = a1b + ar.b1 (4-acc)
        const float* ar = &a1wjs[t * 64];
        float s0 = 0.f, s1 = 0.f, s2 = 0.f, s3 = 0.f;
        #pragma unroll
        for (int f = 0; f < 64; f += 4) {
            s0 += ar[f + 0] * b1s[f + 0];
            s1 += ar[f + 1] * b1s[f + 1];
            s2 += ar[f + 2] * b1s[f + 2];
            s3 += ar[f + 3] * b1s[f + 3];
        }
        cs[t] = a1b[t] + (s0 + s1) + (s2 + s3);
    }
    __syncthreads();

    // ---- phase 2: tree-sum fold partials -> us ----
    {
        float s0 = 0.f, s1 = 0.f;
        #pragma unroll
        for (int c = 0; c < 8; c += 2) { s0 += qs8[c][t]; s1 += qs8[c + 1][t]; }
        us[t] = s0 + s1;
    }
    __syncthreads();

    // ---- phase 3: scores — 16 threads/row, 4-round shfl, exp ----
    {
        float s[NH];
        #pragma unroll
        for (int h = 0; h < NH; h++) {
            float4 u4 = ((const float4*)us)[h * 16 + u];
            s[h] = u4.x * x4.x + u4.y * x4.y + u4.z * x4.z + u4.w * x4.w;
        }
        #pragma unroll
        for (int o = 1; o < 16; o <<= 1) {
            #pragma unroll
            for (int h = 0; h < NH; h++)
                s[h] += __shfl_xor_sync(0xffffffffu, s[h], o);
        }
        if (u < NH) {
            float sv = s[0];
            #pragma unroll
            for (int h = 1; h < NH; h++) sv = (u == h) ? s[h] : sv;
            es[g * 8 + u] = __expf(sv + cs[u]);
        }
    }
    __syncthreads();

    // ---- phase 4: q partial (f-parallel, 8 j-lanes, float4 es reads) ----
    {
        const int f = t & 63, l = t >> 6;
        float acc[NH];
        #pragma unroll
        for (int h = 0; h < NH; h++) acc[h] = 0.f;
        #pragma unroll
        for (int jj = l; jj < RPB; jj += 8) {
            float4 e0 = ((const float4*)&es[jj * 8])[0];
            float4 e1 = ((const float4*)&es[jj * 8])[1];
            float xv = xs[jj * 68 + f];
            acc[0] += e0.x * xv; acc[1] += e0.y * xv;
            acc[2] += e0.z * xv; acc[3] += e0.w * xv;
            acc[4] += e1.x * xv; acc[5] += e1.y * xv;
            acc[6] += e1.z * xv; acc[7] += e1.w * xv;
        }
        #pragma unroll
        for (int h = 0; h < NH; h++) qs8[l][h * 64 + f] = acc[h];
    }
    __syncthreads();

    // ---- phase 5: tree-sum + REDG publish ----
    {
        float s0 = 0.f, s1 = 0.f;
        #pragma unroll
        for (int c = 0; c < 8; c += 2) { s0 += qs8[c][t]; s1 += qs8[c + 1][t]; }
        atomicAdd(&g_q[t], s0 + s1);
    }
    if (t < NH) {
        float z0 = 0.f, z1 = 0.f, z2 = 0.f, z3 = 0.f;
        #pragma unroll
        for (int jj = 0; jj < RPB; jj += 4) {
            z0 += es[(jj + 0) * 8 + t];
            z1 += es[(jj + 1) * 8 + t];
            z2 += es[(jj + 2) * 8 + t];
            z3 += es[(jj + 3) * 8 + t];
        }
        atomicAdd(&g_Z[t], (z0 + z1) + (z2 + z3));
    }

    // ---- grid sync; stage W2/b2 inside the poll window ----
    __threadfence();
    __syncthreads();
    if (t == 0) atomicAdd(&g_arrive, 1);
    ((float4*)W2s)[t] = ((const float4*)W2)[t];
    if (t < NH) ((float4*)b2s)[t] = ((const float4*)b2)[t];
    if (t == 0) {
        while (*(volatile unsigned*)&g_arrive < NBLK) __nanosleep(32);
    }
    __syncthreads();
    __threadfence();

    // ---- tail (R6 lean structure) ----
    {
        const int f = t >> 3, h = t & 7;
        float v = g_q[h * 64 + f] / g_Z[h];
        v += __shfl_xor_sync(0xffffffffu, v, 1);
        v += __shfl_xor_sync(0xffffffffu, v, 2);
        v += __shfl_xor_sync(0xffffffffu, v, 4);
        if (h == 0) qbar[f] = v * (1.f / NH);
    }
    __syncthreads();
    if (t == 0) s_last = (atomicAdd(&g_exit, 1) == NBLK - 1);  // g_q consumed

    {   // os[m] = elu(lrelu(W1s[m,:].qbar + b1[m])) : 8 threads/output
        const int m = t >> 3, kc = t & 7;
        const float* wr = &W1s[m * 65 + kc * 8];
        const float* q8 = &qbar[kc * 8];
        float s = wr[0] * q8[0] + wr[1] * q8[1] + wr[2] * q8[2] + wr[3] * q8[3]
                + wr[4] * q8[4] + wr[5] * q8[5] + wr[6] * q8[6] + wr[7] * q8[7];
        s += __shfl_xor_sync(0xffffffffu, s, 1);
        s += __shfl_xor_sync(0xffffffffu, s, 2);
        s += __shfl_xor_sync(0xffffffffu, s, 4);
        if (kc == 0) {
            s += b1s[m];
            float lr = s > 0.f ? s : 0.2f * s;
            os[m] = lr > 0.f ? lr : (__expf(lr) - 1.f);
        }
    }
    __syncthreads();
    {   // fs[m] = lrelu(W2s[m,:].os + b2[m]) : 16 threads/output
        const int m = t >> 4, kc = t & 15;
        float4 w = ((const float4*)W2s)[m * 16 + kc];
        const float* o4 = &os[kc * 4];
        float s = w.x * o4[0] + w.y * o4[1] + w.z * o4[2] + w.w * o4[3];
        s += __shfl_xor_sync(0xffffffffu, s, 1);
        s += __shfl_xor_sync(0xffffffffu, s, 2);
        s += __shfl_xor_sync(0xffffffffu, s, 4);
        s += __shfl_xor_sync(0xffffffffu, s, 8);
        if (kc == 0) {
            s += b2s[m];
            fs[m] = s > 0.f ? s : 0.2f * s;
        }
    }
    __syncthreads();

    // ---- output: 32 rows x 32 cols per block = 256 float4 ----
    if (t < 256) {
        int f0 = (t & 7) << 2;
        float4 v = make_float4(fs[f0], fs[f0 + 1], fs[f0 + 2], fs[f0 + 3]);
        ((float4*)out)[b * 256 + t] = v;
    }

    // ---- reset for next graph replay (last exiting block; all reads done) ----
    __syncthreads();
    if (s_last) {
        g_q[t] = 0.f;
        if (t < NH) g_Z[t] = 0.f;
        if (t == 0) { g_arrive = 0; g_exit = 0; }
    }
}

extern "C" void kernel_launch(void* const* d_in, const int* in_sizes, int n_in,
                              void* d_out, int out_size) {
    const float* x   = (const float*)d_in[0];
    const float* W1  = (const float*)d_in[1];
    const float* b1  = (const float*)d_in[2];
    const float* a1w = (const float*)d_in[3];
    const float* a1b = (const float*)d_in[4];
    const float* W2  = (const float*)d_in[5];
    const float* b2  = (const float*)d_in[6];
    // d_in[7] (a2_w), d_in[8] (a2_b): provably no effect on output.

    gat_fused<<<NBLK, NT>>>(x, W1, b1, a1w, a1b, W2, b2, (float*)d_out);
}